// round 17
// baseline (speedup 1.0000x reference)
#include <cuda_runtime.h>
#include <math.h>
#include <cstdint>

// Problem constants
#define HD   96
#define WD   96
// tile
#define PXB  16     // pixels (w) per block
#define ROWS 4      // output rows per block (2 pairs)
#define XW   24     // halo window cols [w0-4, w0+20), 4-aligned
#define CHS  193    // channel stride in floats: 8*24+1 (odd -> conflict-free lane stride)

// shared layout (floats)
#define IN_SH_F   (128*CHS)          // 24704
#define CONV_SH_F (PXB*32*36)        // 18432 : conv[p][o*8+j][z] ; epilogue: staging 256x65
#define WC_SH_F   800                // [o][ky][kx][j]
#define MP_SH_F   512                // [o][t][bb][k]  (k contiguous -> LDS.128)
#define MA_PAD    16
#define MA_SH_F   512
#define MB_SH_F   128
#define SMEM_F (IN_SH_F + CONV_SH_F + WC_SH_F + MP_SH_F + MA_PAD + MA_SH_F + MB_SH_F)

// prep scratch: [0:512) mp normalized+relayout, [512:1024) ma relayout, [1024:1152) mb
__device__ float g_prep[1152];

// Blackwell packed fp32 ops (b64 register pairs)
#define FMA_F32X2(d, a, b, c) \
    asm("fma.rn.f32x2 %0, %1, %2, %3;" : "=l"(d) : "l"(a), "l"(b), "l"(c))
#define PACK_DUP_F32X2(d, v) \
    asm("mov.b64 %0, {%1, %1};" : "=l"(d) : "f"(v))
#define UNPACK_F32X2(lo, hi, in) \
    asm("mov.b64 {%0, %1}, %2;" : "=f"(lo), "=f"(hi) : "l"(in))
// group-scoped barrier: 4-warp (128-thread) named barrier
#define GROUP_BAR(id) \
    asm volatile("bar.sync %0, 128;" :: "r"(id) : "memory")

__global__ void prep_kernel(const float* __restrict__ Wp,
                            const float* __restrict__ Wa,
                            const float* __restrict__ ba)
{
    int tid = threadIdx.x;
    {
        int q8 = tid >> 4;           // o*8 + t
        int bb = (tid >> 2) & 3;
        int k  = tid & 3;
        int o  = q8 >> 3, t = q8 & 7;
        int src = o*128 + t*16 + k*4 + bb;
        float s = 0.f;
        #pragma unroll
        for (int kk = 0; kk < 4; kk++) {
            float v = Wp[o*128 + t*16 + kk*4 + bb];
            s += v * v;
        }
        float nrm = sqrtf(fmaxf(s, 1e-12f));
        g_prep[tid]       = Wp[src] / nrm;
        g_prep[512 + tid] = Wa[src];
    }
    if (tid < 128) {
        int bb = tid & 3, t = (tid >> 2) & 7, o = tid >> 5;
        float sm = 0.f;
        #pragma unroll
        for (int k = 0; k < 4; k++) sm += Wa[o*128 + t*16 + k*4 + bb];
        g_prep[1024 + tid] = ba[o*8 + t] * sm;
    }
}

// segmented 16-lane norms via merge-route butterfly (8 shfl), then squash
__device__ __forceinline__ void routing_norms(const float* pt, bool app,
                                              int l0, int l1, float* v_)
{
    const unsigned FULL = 0xffffffffu;
    float xv[4];
    #pragma unroll
    for (int tt = 0; tt < 4; tt++)
        xv[tt] = app ? pt[tt]*pt[tt] : fabsf(pt[tt]);
    float ka = xv[l0],      sa = xv[l0 ^ 1];
    float kb = xv[2 + l0],  sb = xv[2 + (l0 ^ 1)];
    float ra  = __shfl_xor_sync(FULL, sa, 1);
    float rb2 = __shfl_xor_sync(FULL, sb, 1);
    float ya = app ? (ka + ra)  : fmaxf(ka, ra);
    float yb = app ? (kb + rb2) : fmaxf(kb, rb2);
    float kc = l1 ? yb : ya;
    float sc = l1 ? ya : yb;
    float rc = __shfl_xor_sync(FULL, sc, 2);
    float z  = app ? (kc + rc) : fmaxf(kc, rc);
    float z4 = __shfl_xor_sync(FULL, z, 4);
    z = app ? (z + z4) : fmaxf(z, z4);
    float z8 = __shfl_xor_sync(FULL, z, 8);
    z = app ? (z + z8) : fmaxf(z, z8);            // z = S[lane&3]
    float w  = __shfl_xor_sync(FULL, z, 1);
    float sE = l0 ? w : z;
    float sO = l0 ? z : w;
    float rE = __shfl_xor_sync(FULL, sE, 2);
    float rO = __shfl_xor_sync(FULL, sO, 2);
    float S[4];
    S[0] = l1 ? rE : sE;
    S[1] = l1 ? rO : sO;
    S[2] = l1 ? sE : rE;
    S[3] = l1 ? sO : rO;
    #pragma unroll
    for (int tt = 0; tt < 4; tt++) {
        if (app) {
            float x = S[tt];
            v_[tt] = __fdividef(x, 1.f + x) * pt[tt] * rsqrtf(x + 1e-9f);
        } else {
            v_[tt] = __fdividef(pt[tt], S[tt]);
        }
    }
}

// multi-value butterfly: returns R*other for this lane's owned b (15+1 shfl)
__device__ __forceinline__ float routing_update(const float* uh, const float* v_,
                                                bool x0, bool x1, bool x2, bool x3)
{
    const unsigned FULL = 0xffffffffu;
    float t8[8];
    #pragma unroll
    for (int j = 0; j < 8; j++) {
        float sa = uh[2*j]     * v_[(2*j)     & 3];
        float sb = uh[2*j + 1] * v_[(2*j + 1) & 3];
        float keep = x0 ? sb : sa;
        float send = x0 ? sa : sb;
        t8[j] = keep + __shfl_xor_sync(FULL, send, 1);
    }
    float t4[4];
    #pragma unroll
    for (int j = 0; j < 4; j++) {
        float keep = x1 ? t8[2*j + 1] : t8[2*j];
        float send = x1 ? t8[2*j]     : t8[2*j + 1];
        t4[j] = keep + __shfl_xor_sync(FULL, send, 2);
    }
    float t2[2];
    #pragma unroll
    for (int j = 0; j < 2; j++) {
        float keep = x2 ? t4[2*j + 1] : t4[2*j];
        float send = x2 ? t4[2*j]     : t4[2*j + 1];
        t2[j] = keep + __shfl_xor_sync(FULL, send, 4);
    }
    float keep = x3 ? t2[1] : t2[0];
    float send = x3 ? t2[0] : t2[1];
    float R = keep + __shfl_xor_sync(FULL, send, 8);
    float other = __shfl_xor_sync(FULL, R, 16);
    return R * other;
}

__global__ void __launch_bounds__(1024, 1)
caps2d_fused_kernel(const float* __restrict__ inp,
                    const float* __restrict__ Wc,
                    float* __restrict__ out)
{
    extern __shared__ float smem[];
    float* in_sh   = smem;
    float* conv_sh = in_sh + IN_SH_F;
    float* wc_sh   = conv_sh + CONV_SH_F;
    float* mp_sh   = wc_sh + WC_SH_F;
    float* ma_sh   = mp_sh + MP_SH_F + MA_PAD;
    float* mb_sh   = ma_sh + MA_SH_F;

    const int tid  = threadIdx.x;
    const int warp = tid >> 5;
    const int lane = tid & 31;
    const int w0   = blockIdx.x * PXB;
    const int hh0  = blockIdx.y * ROWS;
    const int n    = blockIdx.z;

    // ---- load conv weights + prepped matrices ----
    if (tid < 800) wc_sh[tid] = Wc[tid];
    if (tid < 512) {
        mp_sh[tid] = g_prep[tid];
        ma_sh[tid] = g_prep[512 + tid];
    }
    if (tid < 128) mb_sh[tid] = g_prep[1024 + tid];

    // ---- vector halo load: 8 rows x 24 cols x 128 ch ----
    {
        int id  = tid & 63;          // (y,g): 8 rows x 6 float4 groups (48 of 64 used)
        int y   = id >> 3;           // 0..7
        int g   = id & 7;            // 0..7, valid g<6
        int ch0 = tid >> 6;          // 0..15 ; ch = ch0 + 16*c
        int gy  = hh0 - 2 + y;
        int gx0 = w0 - 4 + g*4;
        bool act = (g < 6);
        bool ok  = act && (gy >= 0) && (gy < HD) && (gx0 >= 0) && (gx0 + 3 < WD);
        const float* src = inp + ((n*128 + ch0)*HD + gy)*WD + gx0;
        float* dst = in_sh + ch0*CHS + y*XW + g*4;
        #pragma unroll
        for (int c = 0; c < 8; c++) {
            float4 v = make_float4(0.f, 0.f, 0.f, 0.f);
            if (ok) v = *reinterpret_cast<const float4*>(src);
            if (act) { dst[0] = v.x; dst[1] = v.y; dst[2] = v.z; dst[3] = v.w; }
            src += 16*HD*WD;
            dst += 16*CHS;
        }
    }
    __syncthreads();

    // routing-role constants
    const int half = warp & 1;
    const int p    = warp >> 1;          // 0..15
    const int gw   = w0 + p;
    const int a_   = (lane >> 2) & 3;
    const int bb   = lane & 3;
    const bool app = (lane >> 4) != 0;
    const float cx = (float)gw * (1.f/96.f);
    // conv-role constants
    const int o_c  = warp & 3;
    const int p0   = (warp >> 2) * 2;    // 0,2,..,14
    const int barid = 1 + (warp >> 2);   // 1..8
    const unsigned FULL = 0xffffffffu;
    const bool x0 = (lane & 1) != 0;
    const bool x1 = (lane & 2) != 0;
    const bool x2 = (lane & 4) != 0;
    const bool x3 = (lane & 8) != 0;
    const int l0 = lane & 1;
    const int l1 = (lane >> 1) & 1;

    const float* ib  = in_sh + (o_c*32 + lane)*CHS;
    const float* wcb = wc_sh + o_c*200;
    float* csh = conv_sh + p * (32*36);

    float vr[16];   // routing outputs, 4 per row, held to the epilogue

    #pragma unroll
    for (int pr = 0; pr < 2; pr++) {
        float uh_a[16], uh_b[16];

        #pragma unroll
        for (int sub = 0; sub < 2; sub++) {
            const int hr = pr*2 + sub;
            // ---- phase 1: depthwise 5x5 conv, packed f32x2 (j-pairs) ----
            {
                uint64_t acc2[8];
                #pragma unroll
                for (int q = 0; q < 8; q++) acc2[q] = 0ull;
                #pragma unroll
                for (int ky = 0; ky < 5; ky++) {
                    float r[6];
                    #pragma unroll
                    for (int q = 0; q < 6; q++) r[q] = ib[(hr + ky)*XW + p0 + 2 + q];
                    #pragma unroll
                    for (int kx = 0; kx < 5; kx++) {
                        const ulonglong2 wA = *reinterpret_cast<const ulonglong2*>(wcb + (ky*5 + kx)*8);
                        const ulonglong2 wB = *reinterpret_cast<const ulonglong2*>(wcb + (ky*5 + kx)*8 + 4);
                        uint64_t va2, vb2;
                        PACK_DUP_F32X2(va2, r[kx]);
                        PACK_DUP_F32X2(vb2, r[kx + 1]);
                        FMA_F32X2(acc2[0], va2, wA.x, acc2[0]);
                        FMA_F32X2(acc2[1], va2, wA.y, acc2[1]);
                        FMA_F32X2(acc2[2], va2, wB.x, acc2[2]);
                        FMA_F32X2(acc2[3], va2, wB.y, acc2[3]);
                        FMA_F32X2(acc2[4], vb2, wA.x, acc2[4]);
                        FMA_F32X2(acc2[5], vb2, wA.y, acc2[5]);
                        FMA_F32X2(acc2[6], vb2, wB.x, acc2[6]);
                        FMA_F32X2(acc2[7], vb2, wB.y, acc2[7]);
                    }
                }
                float* c0 = conv_sh + p0*(32*36)       + (o_c*8)*36 + lane;
                float* c1 = conv_sh + (p0 + 1)*(32*36) + (o_c*8)*36 + lane;
                #pragma unroll
                for (int jp = 0; jp < 4; jp++) {
                    float lo, hi;
                    UNPACK_F32X2(lo, hi, acc2[jp]);
                    c0[(2*jp)*36]     = lo;
                    c0[(2*jp + 1)*36] = hi;
                }
                #pragma unroll
                for (int jp = 0; jp < 4; jp++) {
                    float lo, hi;
                    UNPACK_F32X2(lo, hi, acc2[4 + jp]);
                    c1[(2*jp)*36]     = lo;
                    c1[(2*jp + 1)*36] = hi;
                }
            }
            GROUP_BAR(barid);   // group's conv tiles ready

            // ---- phase 2: u_hat -> uh_a (sub 0) / uh_b (sub 1) ----
            const float cy = (float)(hh0 + hr) * (1.f/96.f);
            const float coordv = app ? 0.f : (bb == 0 ? cx : (bb == 1 ? cy : 0.f));
            float* uh = sub ? uh_b : uh_a;
            #pragma unroll
            for (int o = 0; o < 4; o++) {
                #pragma unroll
                for (int tt = 0; tt < 4; tt++) {
                    const int t  = half*4 + tt;
                    const int j  = (app ? 4 : 0) + (t >> 1);
                    const int zb = ((t & 1) << 4) + (a_ << 2);
                    const float4 cv = *reinterpret_cast<const float4*>(csh + (o*8 + j)*36 + zb);
                    const float* msrc = (app ? ma_sh : mp_sh) + ((o*8 + t)*4 + bb)*4;
                    const float4 m = *reinterpret_cast<const float4*>(msrc);
                    float s0 = app ? mb_sh[(o*8 + t)*4 + bb] : 0.f;
                    float s;
                    s = fmaf(cv.x, m.x, s0);
                    s = fmaf(cv.y, m.y, s);
                    s = fmaf(cv.z, m.z, s);
                    s = fmaf(cv.w, m.w, s);
                    s = fmaf(cv.w, coordv, s);
                    uh[o*4 + tt] = s;
                }
            }
            GROUP_BAR(barid);   // group's conv_sh reads done (next conv may overwrite)
        }

        // ---- phase 3: DUAL routing, rows (2pr, 2pr+1) interleaved ----
        float* va  = vr + (pr*2)*4;
        float* vb_ = vr + (pr*2 + 1)*4;
        float bq_a = 0.f, bq_b = 0.f;
        for (int iter = 0; iter < 3; iter++) {
            float pt_a[4], pt_b[4];
            if (iter == 0) {
                #pragma unroll
                for (int tt = 0; tt < 4; tt++) {
                    pt_a[tt] = 0.5f * (uh_a[tt] + uh_a[4 + tt] + uh_a[8 + tt] + uh_a[12 + tt]);
                    pt_b[tt] = 0.5f * (uh_b[tt] + uh_b[4 + tt] + uh_b[8 + tt] + uh_b[12 + tt]);
                }
            } else {
                float rq_a = __fdividef(1.f, 1.f + __expf(-bq_a));
                float rq_b = __fdividef(1.f, 1.f + __expf(-bq_b));
                #pragma unroll
                for (int tt = 0; tt < 4; tt++) {
                    float sA = 0.f, sB = 0.f;
                    #pragma unroll
                    for (int o = 0; o < 4; o++) {
                        int idx = (lane & 16) | (o*4 + tt);
                        float rA = __shfl_sync(FULL, rq_a, idx);
                        float rB = __shfl_sync(FULL, rq_b, idx);
                        sA = fmaf(uh_a[o*4 + tt], rA, sA);
                        sB = fmaf(uh_b[o*4 + tt], rB, sB);
                    }
                    pt_a[tt] = sA;
                    pt_b[tt] = sB;
                }
            }
            routing_norms(pt_a, app, l0, l1, va);
            routing_norms(pt_b, app, l0, l1, vb_);
            if (iter == 2) break;
            bq_a += routing_update(uh_a, va,  x0, x1, x2, x3);
            bq_b += routing_update(uh_b, vb_, x0, x1, x2, x3);
        }
    }

    __syncthreads();   // realign all groups before conv_sh is repurposed

    // ---- epilogue: stage all 4 rows, conv_sh reused as os[row][hr*16+p], stride 65 ----
    #pragma unroll
    for (int hr = 0; hr < ROWS; hr++)
        #pragma unroll
        for (int tt = 0; tt < 4; tt++)
            conv_sh[((half*4 + tt)*32 + lane)*65 + hr*16 + p] = vr[hr*4 + tt];
    __syncthreads();

    // ---- coalesced writeout: 16 independent STG per thread ----
    {
        int x  = tid & 15;
        int hw = (tid >> 4) & 3;
        int r0 = tid >> 6;          // 0..15
        const float* os = conv_sh + hw*16 + x;
        float* ob = out + n*256*(HD*WD) + (hh0 + hw)*WD + w0 + x;
        #pragma unroll
        for (int k = 0; k < 16; k++) {
            int row = r0 + 16*k;
            ob[row*(HD*WD)] = os[row*65];
        }
    }
}

extern "C" void kernel_launch(void* const* d_in, const int* in_sizes, int n_in,
                              void* d_out, int out_size)
{
    const float* inp = (const float*)d_in[0];   // (4,4,32,96,96)
    const float* Wc  = (const float*)d_in[1];   // (4,5,5,1,8)
    const float* Wp  = (const float*)d_in[2];   // (4,16,8)
    const float* Wa  = (const float*)d_in[3];   // (4,16,8)
    const float* ba  = (const float*)d_in[4];   // (4,8)
    float* out = (float*)d_out;                 // (4,8,32,96,96)

    // weight prep (normalization/relayout/bias-fold) once
    prep_kernel<<<1, 512>>>(Wp, Wa, ba);

    const int smem_bytes = SMEM_F * (int)sizeof(float);
    cudaFuncSetAttribute(caps2d_fused_kernel,
                         cudaFuncAttributeMaxDynamicSharedMemorySize, smem_bytes);

    dim3 grid(WD / PXB, HD / ROWS, 4);   // (6, 24, 4)
    dim3 block(1024);
    caps2d_fused_kernel<<<grid, block, smem_bytes>>>(inp, Wc, out);
}